// round 14
// baseline (speedup 1.0000x reference)
#include <cuda_runtime.h>
#include <cuda_bf16.h>

// Problem dims
#define BB    32
#define SS    512
#define WIN   5
#define EMB   300
#define HH    300
#define K1    1500        // EMB*WIN
#define NOUT  128
#define MROWS (BB*SS)     // 16384

// ------------------------------------------------------------------
// Scratch (static device globals)
// ------------------------------------------------------------------
__device__ float g_XE[(size_t)MROWS * K1];   // relu(embedded)
__device__ float g_A [(size_t)MROWS * HH];   // A1 pre-activation
__device__ float g_H1[(size_t)MROWS * HH];   // layer1 hidden states [s*32+b][300]
__device__ float g_H2[(size_t)MROWS * HH];   // layer2 hidden states

// ------------------------------------------------------------------
// helpers
// ------------------------------------------------------------------
__device__ __forceinline__ void ffma2(unsigned long long &d,
                                      unsigned long long a,
                                      unsigned long long b) {
    asm("fma.rn.f32x2 %0, %1, %2, %0;" : "+l"(d) : "l"(a), "l"(b));
}
__device__ __forceinline__ unsigned long long pack2(float lo, float hi) {
    unsigned long long r;
    asm("mov.b64 %0, {%1, %2};" : "=l"(r) : "f"(lo), "f"(hi));
    return r;
}
__device__ __forceinline__ void unpack2(unsigned long long v, float &lo, float &hi) {
    asm("mov.b64 {%0, %1}, %2;" : "=f"(lo), "=f"(hi) : "l"(v));
}
__device__ __forceinline__ unsigned smem_u32(const void *p) {
    unsigned a;
    asm("{ .reg .u64 t; cvta.to.shared.u64 t, %1; cvt.u32.u64 %0, t; }"
        : "=r"(a) : "l"(p));
    return a;
}
// tanh via MUFU: 1 - 2/(exp2(2x*log2e)+1). abs err ~1e-7, no division.
__device__ __forceinline__ float tanh_fast(float x) {
    float e;
    asm("ex2.approx.f32 %0, %1;" : "=f"(e) : "f"(x * 2.88539008177792681f));
    float r;
    asm("rcp.approx.f32 %0, %1;" : "=f"(r) : "f"(e + 1.0f));
    return fmaf(-2.0f, r, 1.0f);
}

// ------------------------------------------------------------------
// Kernel 1: embedding gather + relu
// ------------------------------------------------------------------
__global__ void embed_kernel(const int *__restrict__ x,
                             const float *__restrict__ emb) {
    int m = blockIdx.x;            // m = s*32 + b
    int s = m >> 5, b = m & 31;
    __shared__ int idx[WIN];
    if (threadIdx.x < WIN) idx[threadIdx.x] = x[(b * SS + s) * WIN + threadIdx.x];
    __syncthreads();
    float4 *out4 = reinterpret_cast<float4 *>(g_XE + (size_t)m * K1);
    for (int i = threadIdx.x; i < K1 / 4; i += blockDim.x) {
        int e4 = i * 4;
        int w = e4 / EMB;
        int e = e4 - w * EMB;
        float4 v = *reinterpret_cast<const float4 *>(emb + (size_t)idx[w] * EMB + e);
        v.x = fmaxf(v.x, 0.f); v.y = fmaxf(v.y, 0.f);
        v.z = fmaxf(v.z, 0.f); v.w = fmaxf(v.w, 0.f);
        out4[i] = v;
    }
}

// ------------------------------------------------------------------
// GEMM (proven R8): BM=128, BN=128, BK=16, 256 thr, 8x8 tile, dbl-buffered.
// ------------------------------------------------------------------
template <bool PERM>
__global__ __launch_bounds__(256)
void gemm_nt(const float *__restrict__ A, const float *__restrict__ Bw,
             const float *__restrict__ b1, const float *__restrict__ b2,
             float *__restrict__ C, int M, int N, int K, int ldc) {
    __shared__ __align__(16) float As[2][16][132];
    __shared__ __align__(16) float Bs[2][16][132];

    const int tid = threadIdx.x;
    const int m0 = blockIdx.y * 128;
    const int n0 = blockIdx.x * 128;
    const int tx = tid & 15;
    const int ty = tid >> 4;
    const int lr = tid >> 1;
    const int lk = (tid & 1) * 8;

    unsigned long long acc[8][4];
#pragma unroll
    for (int i = 0; i < 8; i++)
#pragma unroll
        for (int j = 0; j < 4; j++) acc[i][j] = 0ULL;

    const int KT = (K + 15) >> 4;

    {
        float4 a0 = make_float4(0.f,0.f,0.f,0.f), a1 = a0, v0 = a0, v1 = a0;
        int kk = lk;
        const float *ap = A + (size_t)(m0 + lr) * K;
        if (kk     < K) a0 = *reinterpret_cast<const float4 *>(ap + kk);
        if (kk + 4 < K) a1 = *reinterpret_cast<const float4 *>(ap + kk + 4);
        if (n0 + lr < N) {
            const float *bp = Bw + (size_t)(n0 + lr) * K;
            if (kk     < K) v0 = *reinterpret_cast<const float4 *>(bp + kk);
            if (kk + 4 < K) v1 = *reinterpret_cast<const float4 *>(bp + kk + 4);
        }
        As[0][lk+0][lr]=a0.x; As[0][lk+1][lr]=a0.y; As[0][lk+2][lr]=a0.z; As[0][lk+3][lr]=a0.w;
        As[0][lk+4][lr]=a1.x; As[0][lk+5][lr]=a1.y; As[0][lk+6][lr]=a1.z; As[0][lk+7][lr]=a1.w;
        Bs[0][lk+0][lr]=v0.x; Bs[0][lk+1][lr]=v0.y; Bs[0][lk+2][lr]=v0.z; Bs[0][lk+3][lr]=v0.w;
        Bs[0][lk+4][lr]=v1.x; Bs[0][lk+5][lr]=v1.y; Bs[0][lk+6][lr]=v1.z; Bs[0][lk+7][lr]=v1.w;
    }
    __syncthreads();

    for (int kt = 0; kt < KT; kt++) {
        const int cb = kt & 1;
        float4 a0 = make_float4(0.f,0.f,0.f,0.f), a1 = a0, v0 = a0, v1 = a0;
        const bool more = (kt + 1 < KT);
        if (more) {
            int kk = (kt + 1) * 16 + lk;
            const float *ap = A + (size_t)(m0 + lr) * K;
            if (kk     < K) a0 = *reinterpret_cast<const float4 *>(ap + kk);
            if (kk + 4 < K) a1 = *reinterpret_cast<const float4 *>(ap + kk + 4);
            if (n0 + lr < N) {
                const float *bp = Bw + (size_t)(n0 + lr) * K;
                if (kk     < K) v0 = *reinterpret_cast<const float4 *>(bp + kk);
                if (kk + 4 < K) v1 = *reinterpret_cast<const float4 *>(bp + kk + 4);
            }
        }

#pragma unroll
        for (int k = 0; k < 16; k++) {
            float4 aA = *reinterpret_cast<const float4 *>(&As[cb][k][ty * 8]);
            float4 aB = *reinterpret_cast<const float4 *>(&As[cb][k][ty * 8 + 4]);
            ulonglong2 bA = *reinterpret_cast<const ulonglong2 *>(&Bs[cb][k][tx * 8]);
            ulonglong2 bB = *reinterpret_cast<const ulonglong2 *>(&Bs[cb][k][tx * 8 + 4]);
            unsigned long long p0 = pack2(aA.x, aA.x), p1 = pack2(aA.y, aA.y);
            unsigned long long p2 = pack2(aA.z, aA.z), p3 = pack2(aA.w, aA.w);
            unsigned long long p4 = pack2(aB.x, aB.x), p5 = pack2(aB.y, aB.y);
            unsigned long long p6 = pack2(aB.z, aB.z), p7 = pack2(aB.w, aB.w);
            ffma2(acc[0][0], p0, bA.x); ffma2(acc[0][1], p0, bA.y);
            ffma2(acc[0][2], p0, bB.x); ffma2(acc[0][3], p0, bB.y);
            ffma2(acc[1][0], p1, bA.x); ffma2(acc[1][1], p1, bA.y);
            ffma2(acc[1][2], p1, bB.x); ffma2(acc[1][3], p1, bB.y);
            ffma2(acc[2][0], p2, bA.x); ffma2(acc[2][1], p2, bA.y);
            ffma2(acc[2][2], p2, bB.x); ffma2(acc[2][3], p2, bB.y);
            ffma2(acc[3][0], p3, bA.x); ffma2(acc[3][1], p3, bA.y);
            ffma2(acc[3][2], p3, bB.x); ffma2(acc[3][3], p3, bB.y);
            ffma2(acc[4][0], p4, bA.x); ffma2(acc[4][1], p4, bA.y);
            ffma2(acc[4][2], p4, bB.x); ffma2(acc[4][3], p4, bB.y);
            ffma2(acc[5][0], p5, bA.x); ffma2(acc[5][1], p5, bA.y);
            ffma2(acc[5][2], p5, bB.x); ffma2(acc[5][3], p5, bB.y);
            ffma2(acc[6][0], p6, bA.x); ffma2(acc[6][1], p6, bA.y);
            ffma2(acc[6][2], p6, bB.x); ffma2(acc[6][3], p6, bB.y);
            ffma2(acc[7][0], p7, bA.x); ffma2(acc[7][1], p7, bA.y);
            ffma2(acc[7][2], p7, bB.x); ffma2(acc[7][3], p7, bB.y);
        }

        if (more) {
            const int nb = cb ^ 1;
            As[nb][lk+0][lr]=a0.x; As[nb][lk+1][lr]=a0.y; As[nb][lk+2][lr]=a0.z; As[nb][lk+3][lr]=a0.w;
            As[nb][lk+4][lr]=a1.x; As[nb][lk+5][lr]=a1.y; As[nb][lk+6][lr]=a1.z; As[nb][lk+7][lr]=a1.w;
            Bs[nb][lk+0][lr]=v0.x; Bs[nb][lk+1][lr]=v0.y; Bs[nb][lk+2][lr]=v0.z; Bs[nb][lk+3][lr]=v0.w;
            Bs[nb][lk+4][lr]=v1.x; Bs[nb][lk+5][lr]=v1.y; Bs[nb][lk+6][lr]=v1.z; Bs[nb][lk+7][lr]=v1.w;
        }
        __syncthreads();
    }

    float bias[8];
#pragma unroll
    for (int jj = 0; jj < 8; jj++) {
        int n = n0 + tx * 8 + jj;
        bias[jj] = (n < N) ? (b1[n] + (b2 ? b2[n] : 0.f)) : 0.f;
    }
    const int nbase = n0 + tx * 8;
    const bool full = (nbase + 8 <= N);
#pragma unroll
    for (int i = 0; i < 8; i++) {
        int m = m0 + ty * 8 + i;
        int row = PERM ? ((m & 31) * SS + (m >> 5)) : m;
        float *cp = C + (size_t)row * ldc;
        float v[8];
#pragma unroll
        for (int j = 0; j < 4; j++) {
            float lo, hi;
            unpack2(acc[i][j], lo, hi);
            v[2*j]   = lo + bias[2*j];
            v[2*j+1] = hi + bias[2*j+1];
        }
        if (full) {
            *reinterpret_cast<float4 *>(cp + nbase)     = make_float4(v[0], v[1], v[2], v[3]);
            *reinterpret_cast<float4 *>(cp + nbase + 4) = make_float4(v[4], v[5], v[6], v[7]);
        } else {
#pragma unroll
            for (int j = 0; j < 8; j++)
                if (nbase + j < N) cp[nbase + j] = v[j];
        }
    }
}

// ------------------------------------------------------------------
// FUSED two-layer recurrence, WARP-SPECIALIZED producers:
//   group A (tid <150):  L1 partials for rows u=tid and u+150 (W_hh1 in
//                        regs) -> msg1 sent with minimal pre-send work.
//   group B (tid 150-299): L2 partials (W_ih2 regs + W_hh2 SMEM stream)
//                        for rows u=tid-150 and u+150 -> msg2; runs in the
//                        shadow of msg1 flight + fin1 polls.
// Exchange mechanism unchanged (tagged u64, self-store fast path).
// fin1: tid<75 (h1); fin2: tid in [150,225) (h2).
// ------------------------------------------------------------------
#define OFF_W    0
#define OFF_H1   91200
#define OFF_H2   91840
#define OFF_IB1  92480
#define OFF_IB2  97344
#define REC_SMEM 102208

__global__ void __cluster_dims__(4, 1, 1) __launch_bounds__(320, 1)
rec_fused(const float *__restrict__ Whh1, const float *__restrict__ Wih2,
          const float *__restrict__ Whh2, const float *__restrict__ bih2,
          const float *__restrict__ bhh2, const float *__restrict__ A,
          float *__restrict__ H1out, float *__restrict__ H2out) {
    extern __shared__ __align__(16) char smem[];
    float *h1loc = reinterpret_cast<float *>(smem + OFF_H1);           // [2][80]
    float *h2loc = reinterpret_cast<float *>(smem + OFF_H2);           // [2][80]
    unsigned long long *ib1 = reinterpret_cast<unsigned long long *>(smem + OFF_IB1);
    unsigned long long *ib2 = reinterpret_cast<unsigned long long *>(smem + OFF_IB2);

    const int tid  = threadIdx.x;
    const int rank = blockIdx.x & 3;
    const int b    = blockIdx.x >> 2;
    const bool grpA = tid < 150;
    const bool grpB = (tid >= 150) && (tid < 300);
    const int  u    = grpA ? tid : (grpB ? tid - 150 : 0);   // 0..149
    const int  dst1 = u / 75;          // owner CTA of row u
    const int  dst2 = dst1 + 2;        // owner CTA of row u+150
    const int  slotg = u % 75;         // same slot for both rows

    // register-resident weight slices (2 rows per thread, 75-wide k-slice)
    unsigned long long wA[38], wB[38];
    if (grpA || grpB) {
        const float *base = grpA ? Whh1 : Wih2;
        const float *pa = base + (size_t)u * HH + rank * 75;
        const float *pb = base + (size_t)(u + 150) * HH + rank * 75;
#pragma unroll
        for (int i = 0; i < 37; i++) {
            wA[i] = pack2(pa[2 * i], pa[2 * i + 1]);
            wB[i] = pack2(pb[2 * i], pb[2 * i + 1]);
        }
        wA[37] = pack2(pa[74], 0.f);
        wB[37] = pack2(pb[74], 0.f);
    }

    // fill Whh2s: entry e = q*300 + j  ->  float4 of W_hh2[j, 75r+4q .. +3]
    {
        float4 *Ws = reinterpret_cast<float4 *>(smem + OFF_W);
        for (int e = tid; e < 19 * 300; e += 320) {
            int q = e / 300, j = e - q * 300;
            const float *wp = Whh2 + (size_t)j * HH + rank * 75 + 4 * q;
            int c0 = 4 * q;
            float4 v;
            v.x = (c0 + 0 < 75) ? wp[0] : 0.f;
            v.y = (c0 + 1 < 75) ? wp[1] : 0.f;
            v.z = (c0 + 2 < 75) ? wp[2] : 0.f;
            v.w = (c0 + 3 < 75) ? wp[3] : 0.f;
            Ws[e] = v;
        }
    }
    for (int i = tid; i < 2 * 80; i += 320) { h1loc[i] = 0.f; h2loc[i] = 0.f; }
    for (int i = tid; i < 2 * 4 * 76; i += 320) {
        ib1[i] = 0xFFFFFFFF00000000ULL;
        ib2[i] = 0xFFFFFFFF00000000ULL;
    }
    __syncthreads();
    asm volatile("barrier.cluster.arrive.aligned;" ::: "memory");
    asm volatile("barrier.cluster.wait.aligned;" ::: "memory");

    // remote/self message addresses (per parity). Each producer sends 2
    // msgs: row u -> dst1, row u+150 -> dst2, into its group's inbox.
    unsigned m1_rem[2], m2_rem[2];
    volatile unsigned long long *m1_loc[2], *m2_loc[2];
    bool self1 = false, self2 = false;
    if (grpA || grpB) {
        unsigned long long *ibx = grpA ? ib1 : ib2;
        self1 = (dst1 == rank);
        self2 = (dst2 == rank);
#pragma unroll
        for (int p = 0; p < 2; p++) {
            unsigned l = smem_u32(&ibx[(p * 4 + rank) * 76 + slotg]);
            asm("mapa.shared::cluster.u32 %0, %1, %2;" : "=r"(m1_rem[p]) : "r"(l), "r"(dst1));
            asm("mapa.shared::cluster.u32 %0, %1, %2;" : "=r"(m2_rem[p]) : "r"(l), "r"(dst2));
            m1_loc[p] = &ibx[(p * 4 + rank) * 76 + slotg];
            m2_loc[p] = m1_loc[p];
        }
    }
    // finalizer poll addresses
    const bool fin1 = (tid < 75);
    const bool fin2 = (tid >= 150 && tid < 225);
    const int  sl2  = tid - 150;
    unsigned poll1[2][4], poll2[2][4];
    if (fin1) {
#pragma unroll
        for (int p = 0; p < 2; p++)
#pragma unroll
            for (int s = 0; s < 4; s++)
                poll1[p][s] = smem_u32(&ib1[(p * 4 + s) * 76 + tid]);
    }
    float bias2 = 0.f;
    if (fin2) {
#pragma unroll
        for (int p = 0; p < 2; p++)
#pragma unroll
            for (int s = 0; s < 4; s++)
                poll2[p][s] = smem_u32(&ib2[(p * 4 + s) * 76 + sl2]);
        int row = 75 * rank + sl2;
        bias2 = bih2[row] + bhh2[row];
    }

    const float *arow = A + (size_t)b * HH + rank * 75;
    float *h1row = H1out + (size_t)b * HH + rank * 75;
    float *h2row = H2out + (size_t)b * HH + rank * 75;
    const ulonglong2 *Ws2 = reinterpret_cast<const ulonglong2 *>(smem + OFF_W);

    float a_cur = fin1 ? arow[tid] : 0.f;

    for (int t = 0; t <= SS; t++) {
        const int pb = t & 1;
        float a_nxt = 0.f;
        if (fin1 && t + 1 < SS)
            a_nxt = arow[(size_t)(t + 1) * BB * HH + tid];

        const ulonglong2 *hp1 =
            reinterpret_cast<const ulonglong2 *>(&h1loc[(pb ^ 1) * 80]);

        // ===== group A: L1 partials, minimal work before send =====
        if (grpA && t < SS) {
            unsigned long long cA0 = 0, cA1 = 0, cB0 = 0, cB1 = 0;
#pragma unroll
            for (int k = 0; k < 19; k++) {
                ulonglong2 hv = hp1[k];
                ffma2(cA0, wA[2 * k], hv.x); ffma2(cA1, wA[2 * k + 1], hv.y);
                ffma2(cB0, wB[2 * k], hv.x); ffma2(cB1, wB[2 * k + 1], hv.y);
            }
            float x0, x1, y0, y1;
            unpack2(cA0, x0, x1); unpack2(cA1, y0, y1);
            float pA = (x0 + x1) + (y0 + y1);
            unpack2(cB0, x0, x1); unpack2(cB1, y0, y1);
            float pB = (x0 + x1) + (y0 + y1);
            unsigned long long mA, mB;
            asm("mov.b64 %0, {%1, %2};" : "=l"(mA) : "r"(__float_as_uint(pA)), "r"((unsigned)t));
            asm("mov.b64 %0, {%1, %2};" : "=l"(mB) : "r"(__float_as_uint(pB)), "r"((unsigned)t));
            if (self1) *m1_loc[pb] = mA;
            else asm volatile("st.relaxed.cluster.shared::cluster.b64 [%0], %1;"
                              :: "r"(m1_rem[pb]), "l"(mA) : "memory");
            if (self2) *m2_loc[pb] = mB;
            else asm volatile("st.relaxed.cluster.shared::cluster.b64 [%0], %1;"
                              :: "r"(m2_rem[pb]), "l"(mB) : "memory");
        }

        // ===== group B: L2 partials in the shadow of msg1 flight =====
        if (grpB && t >= 1) {
            const ulonglong2 *hp2 =
                reinterpret_cast<const ulonglong2 *>(&h2loc[pb * 80]);   // h2_{t-2}
            unsigned long long dA0 = 0, dA1 = 0, dB0 = 0, dB1 = 0;
            unsigned long long eA0 = 0, eA1 = 0, eB0 = 0, eB1 = 0;
#pragma unroll
            for (int k = 0; k < 19; k++) {
                ulonglong2 hv = hp1[k];
                ffma2(dA0, wA[2 * k], hv.x); ffma2(dA1, wA[2 * k + 1], hv.y);
                ffma2(dB0, wB[2 * k], hv.x); ffma2(dB1, wB[2 * k + 1], hv.y);
                ulonglong2 h2v = hp2[k];
                ulonglong2 wva = Ws2[k * 300 + u];
                ulonglong2 wvb = Ws2[k * 300 + u + 150];
                ffma2(eA0, wva.x, h2v.x); ffma2(eA1, wva.y, h2v.y);
                ffma2(eB0, wvb.x, h2v.x); ffma2(eB1, wvb.y, h2v.y);
            }
            float x0, x1, y0, y1;
            unpack2(dA0, x0, x1); unpack2(dA1, y0, y1);
            float pA = (x0 + x1) + (y0 + y1);
            unpack2(eA0, x0, x1); unpack2(eA1, y0, y1);
            pA += (x0 + x1) + (y0 + y1);
            unpack2(dB0, x0, x1); unpack2(dB1, y0, y1);
            float pB = (x0 + x1) + (y0 + y1);
            unpack2(eB0, x0, x1); unpack2(eB1, y0, y1);
            pB += (x0 + x1) + (y0 + y1);
            unsigned long long mA, mB;
            asm("mov.b64 %0, {%1, %2};" : "=l"(mA) : "r"(__float_as_uint(pA)), "r"((unsigned)t));
            asm("mov.b64 %0, {%1, %2};" : "=l"(mB) : "r"(__float_as_uint(pB)), "r"((unsigned)t));
            if (self1) *m1_loc[pb] = mA;
            else asm volatile("st.relaxed.cluster.shared::cluster.b64 [%0], %1;"
                              :: "r"(m1_rem[pb]), "l"(mA) : "memory");
            if (self2) *m2_loc[pb] = mB;
            else asm volatile("st.relaxed.cluster.shared::cluster.b64 [%0], %1;"
                              :: "r"(m2_rem[pb]), "l"(mB) : "memory");
        }

        // ===== finalizers =====
        if (fin1 && t < SS) {
            const unsigned want = (unsigned)t;
            float s = a_cur;
#pragma unroll
            for (int src = 0; src < 4; src++) {
                unsigned long long v;
                do {
                    asm volatile("ld.relaxed.cluster.shared::cta.b64 %0, [%1];"
                                 : "=l"(v) : "r"(poll1[pb][src]) : "memory");
                } while ((unsigned)(v >> 32) != want);
                s += __uint_as_float((unsigned)v);
            }
            float hv = tanh_fast(s);
            h1row[(size_t)t * BB * HH + tid] = hv;
            h1loc[pb * 80 + tid] = hv;
        }
        if (fin2 && t >= 1) {
            const unsigned want = (unsigned)t;
            float s = bias2;
#pragma unroll
            for (int src = 0; src < 4; src++) {
                unsigned long long v;
                do {
                    asm volatile("ld.relaxed.cluster.shared::cta.b64 %0, [%1];"
                                 : "=l"(v) : "r"(poll2[pb][src]) : "memory");
                } while ((unsigned)(v >> 32) != want);
                s += __uint_as_float((unsigned)v);
            }
            float hv = tanh_fast(s);
            h2row[(size_t)(t - 1) * BB * HH + sl2] = hv;
            h2loc[(pb ^ 1) * 80 + sl2] = hv;   // read as h2_{(t+1)-2} next step
        }
        a_cur = a_nxt;
        __syncthreads();
    }

    asm volatile("barrier.cluster.arrive.aligned;" ::: "memory");
    asm volatile("barrier.cluster.wait.aligned;" ::: "memory");
}

// ------------------------------------------------------------------
// Launch sequence
// ------------------------------------------------------------------
extern "C" void kernel_launch(void *const *d_in, const int *in_sizes, int n_in,
                              void *d_out, int out_size) {
    const int   *x     = (const int *)d_in[0];
    const float *emb   = (const float *)d_in[1];
    const float *W_ih1 = (const float *)d_in[2];
    const float *W_hh1 = (const float *)d_in[3];
    const float *b_ih1 = (const float *)d_in[4];
    const float *b_hh1 = (const float *)d_in[5];
    const float *W_ih2 = (const float *)d_in[6];
    const float *W_hh2 = (const float *)d_in[7];
    const float *b_ih2 = (const float *)d_in[8];
    const float *b_hh2 = (const float *)d_in[9];
    const float *fc1_w = (const float *)d_in[10];
    const float *fc1_b = (const float *)d_in[11];
    const float *fc2_w = (const float *)d_in[12];
    const float *fc2_b = (const float *)d_in[13];
    float *out = (float *)d_out;

    float *xe, *a, *h1, *h2;
    cudaGetSymbolAddress((void **)&xe, g_XE);
    cudaGetSymbolAddress((void **)&a,  g_A);
    cudaGetSymbolAddress((void **)&h1, g_H1);
    cudaGetSymbolAddress((void **)&h2, g_H2);

    static int smem_set = 0;
    if (!smem_set) {
        cudaFuncSetAttribute(rec_fused,
                             cudaFuncAttributeMaxDynamicSharedMemorySize,
                             REC_SMEM);
        smem_set = 1;
    }

    // 1) embed + relu
    embed_kernel<<<MROWS, 128>>>(x, emb);

    // 2) A1 = XE @ W_ih1^T + (b_ih1 + b_hh1)
    {
        dim3 grid((HH + 127) / 128, MROWS / 128);
        gemm_nt<false><<<grid, 256>>>(xe, W_ih1, b_ih1, b_hh1, a,
                                      MROWS, HH, K1, HH);
    }

    // 3) fused two-layer recurrence -> H1, H2
    rec_fused<<<128, 320, REC_SMEM>>>(W_hh1, W_ih2, W_hh2, b_ih2, b_hh2,
                                      a, h1, h2);

    // 4) projections (permuted store: m = s*32+b -> row b*512+s)
    {
        dim3 grid((NOUT + 127) / 128, MROWS / 128);
        gemm_nt<true><<<grid, 256>>>(h1, fc1_w, fc1_b, nullptr, out,
                                     MROWS, NOUT, HH, NOUT);
        gemm_nt<true><<<grid, 256>>>(h2, fc2_w, fc2_b, nullptr,
                                     out + (size_t)MROWS * NOUT,
                                     MROWS, NOUT, HH, NOUT);
    }
}

// round 15
// speedup vs baseline: 1.1402x; 1.1402x over previous
#include <cuda_runtime.h>
#include <cuda_bf16.h>

// Problem dims
#define BB    32
#define SS    512
#define WIN   5
#define EMB   300
#define HH    300
#define K1    1500        // EMB*WIN
#define NOUT  128
#define MROWS (BB*SS)     // 16384

// ------------------------------------------------------------------
// Scratch (static device globals)
// ------------------------------------------------------------------
__device__ float g_XE[(size_t)MROWS * K1];   // relu(embedded)
__device__ float g_A [(size_t)MROWS * HH];   // A1 pre-activation
__device__ float g_H1[(size_t)MROWS * HH];   // layer1 hidden states [s*32+b][300]
__device__ float g_H2[(size_t)MROWS * HH];   // layer2 hidden states

// ------------------------------------------------------------------
// helpers
// ------------------------------------------------------------------
__device__ __forceinline__ void ffma2(unsigned long long &d,
                                      unsigned long long a,
                                      unsigned long long b) {
    asm("fma.rn.f32x2 %0, %1, %2, %0;" : "+l"(d) : "l"(a), "l"(b));
}
__device__ __forceinline__ unsigned long long pack2(float lo, float hi) {
    unsigned long long r;
    asm("mov.b64 %0, {%1, %2};" : "=l"(r) : "f"(lo), "f"(hi));
    return r;
}
__device__ __forceinline__ void unpack2(unsigned long long v, float &lo, float &hi) {
    asm("mov.b64 {%0, %1}, %2;" : "=f"(lo), "=f"(hi) : "l"(v));
}
__device__ __forceinline__ unsigned smem_u32(const void *p) {
    unsigned a;
    asm("{ .reg .u64 t; cvta.to.shared.u64 t, %1; cvt.u32.u64 %0, t; }"
        : "=r"(a) : "l"(p));
    return a;
}
// tanh via MUFU: 1 - 2/(exp2(2x*log2e)+1). abs err ~1e-7, no division.
__device__ __forceinline__ float tanh_fast(float x) {
    float e;
    asm("ex2.approx.f32 %0, %1;" : "=f"(e) : "f"(x * 2.88539008177792681f));
    float r;
    asm("rcp.approx.f32 %0, %1;" : "=f"(r) : "f"(e + 1.0f));
    return fmaf(-2.0f, r, 1.0f);
}

// ------------------------------------------------------------------
// Kernel 1: embedding gather + relu
// ------------------------------------------------------------------
__global__ void embed_kernel(const int *__restrict__ x,
                             const float *__restrict__ emb) {
    int m = blockIdx.x;            // m = s*32 + b
    int s = m >> 5, b = m & 31;
    __shared__ int idx[WIN];
    if (threadIdx.x < WIN) idx[threadIdx.x] = x[(b * SS + s) * WIN + threadIdx.x];
    __syncthreads();
    float4 *out4 = reinterpret_cast<float4 *>(g_XE + (size_t)m * K1);
    for (int i = threadIdx.x; i < K1 / 4; i += blockDim.x) {
        int e4 = i * 4;
        int w = e4 / EMB;
        int e = e4 - w * EMB;
        float4 v = *reinterpret_cast<const float4 *>(emb + (size_t)idx[w] * EMB + e);
        v.x = fmaxf(v.x, 0.f); v.y = fmaxf(v.y, 0.f);
        v.z = fmaxf(v.z, 0.f); v.w = fmaxf(v.w, 0.f);
        out4[i] = v;
    }
}

// ------------------------------------------------------------------
// GEMM big-tile (proven R8): BM=128, BN=128, BK=16, 256 thr, 8x8 tile.
// Used for A1 (N=300).
// ------------------------------------------------------------------
__global__ __launch_bounds__(256)
void gemm_nt(const float *__restrict__ A, const float *__restrict__ Bw,
             const float *__restrict__ b1, const float *__restrict__ b2,
             float *__restrict__ C, int M, int N, int K, int ldc) {
    __shared__ __align__(16) float As[2][16][132];
    __shared__ __align__(16) float Bs[2][16][132];

    const int tid = threadIdx.x;
    const int m0 = blockIdx.y * 128;
    const int n0 = blockIdx.x * 128;
    const int tx = tid & 15;
    const int ty = tid >> 4;
    const int lr = tid >> 1;
    const int lk = (tid & 1) * 8;

    unsigned long long acc[8][4];
#pragma unroll
    for (int i = 0; i < 8; i++)
#pragma unroll
        for (int j = 0; j < 4; j++) acc[i][j] = 0ULL;

    const int KT = (K + 15) >> 4;

    {
        float4 a0 = make_float4(0.f,0.f,0.f,0.f), a1 = a0, v0 = a0, v1 = a0;
        int kk = lk;
        const float *ap = A + (size_t)(m0 + lr) * K;
        if (kk     < K) a0 = *reinterpret_cast<const float4 *>(ap + kk);
        if (kk + 4 < K) a1 = *reinterpret_cast<const float4 *>(ap + kk + 4);
        if (n0 + lr < N) {
            const float *bp = Bw + (size_t)(n0 + lr) * K;
            if (kk     < K) v0 = *reinterpret_cast<const float4 *>(bp + kk);
            if (kk + 4 < K) v1 = *reinterpret_cast<const float4 *>(bp + kk + 4);
        }
        As[0][lk+0][lr]=a0.x; As[0][lk+1][lr]=a0.y; As[0][lk+2][lr]=a0.z; As[0][lk+3][lr]=a0.w;
        As[0][lk+4][lr]=a1.x; As[0][lk+5][lr]=a1.y; As[0][lk+6][lr]=a1.z; As[0][lk+7][lr]=a1.w;
        Bs[0][lk+0][lr]=v0.x; Bs[0][lk+1][lr]=v0.y; Bs[0][lk+2][lr]=v0.z; Bs[0][lk+3][lr]=v0.w;
        Bs[0][lk+4][lr]=v1.x; Bs[0][lk+5][lr]=v1.y; Bs[0][lk+6][lr]=v1.z; Bs[0][lk+7][lr]=v1.w;
    }
    __syncthreads();

    for (int kt = 0; kt < KT; kt++) {
        const int cb = kt & 1;
        float4 a0 = make_float4(0.f,0.f,0.f,0.f), a1 = a0, v0 = a0, v1 = a0;
        const bool more = (kt + 1 < KT);
        if (more) {
            int kk = (kt + 1) * 16 + lk;
            const float *ap = A + (size_t)(m0 + lr) * K;
            if (kk     < K) a0 = *reinterpret_cast<const float4 *>(ap + kk);
            if (kk + 4 < K) a1 = *reinterpret_cast<const float4 *>(ap + kk + 4);
            if (n0 + lr < N) {
                const float *bp = Bw + (size_t)(n0 + lr) * K;
                if (kk     < K) v0 = *reinterpret_cast<const float4 *>(bp + kk);
                if (kk + 4 < K) v1 = *reinterpret_cast<const float4 *>(bp + kk + 4);
            }
        }

#pragma unroll
        for (int k = 0; k < 16; k++) {
            float4 aA = *reinterpret_cast<const float4 *>(&As[cb][k][ty * 8]);
            float4 aB = *reinterpret_cast<const float4 *>(&As[cb][k][ty * 8 + 4]);
            ulonglong2 bA = *reinterpret_cast<const ulonglong2 *>(&Bs[cb][k][tx * 8]);
            ulonglong2 bB = *reinterpret_cast<const ulonglong2 *>(&Bs[cb][k][tx * 8 + 4]);
            unsigned long long p0 = pack2(aA.x, aA.x), p1 = pack2(aA.y, aA.y);
            unsigned long long p2 = pack2(aA.z, aA.z), p3 = pack2(aA.w, aA.w);
            unsigned long long p4 = pack2(aB.x, aB.x), p5 = pack2(aB.y, aB.y);
            unsigned long long p6 = pack2(aB.z, aB.z), p7 = pack2(aB.w, aB.w);
            ffma2(acc[0][0], p0, bA.x); ffma2(acc[0][1], p0, bA.y);
            ffma2(acc[0][2], p0, bB.x); ffma2(acc[0][3], p0, bB.y);
            ffma2(acc[1][0], p1, bA.x); ffma2(acc[1][1], p1, bA.y);
            ffma2(acc[1][2], p1, bB.x); ffma2(acc[1][3], p1, bB.y);
            ffma2(acc[2][0], p2, bA.x); ffma2(acc[2][1], p2, bA.y);
            ffma2(acc[2][2], p2, bB.x); ffma2(acc[2][3], p2, bB.y);
            ffma2(acc[3][0], p3, bA.x); ffma2(acc[3][1], p3, bA.y);
            ffma2(acc[3][2], p3, bB.x); ffma2(acc[3][3], p3, bB.y);
            ffma2(acc[4][0], p4, bA.x); ffma2(acc[4][1], p4, bA.y);
            ffma2(acc[4][2], p4, bB.x); ffma2(acc[4][3], p4, bB.y);
            ffma2(acc[5][0], p5, bA.x); ffma2(acc[5][1], p5, bA.y);
            ffma2(acc[5][2], p5, bB.x); ffma2(acc[5][3], p5, bB.y);
            ffma2(acc[6][0], p6, bA.x); ffma2(acc[6][1], p6, bA.y);
            ffma2(acc[6][2], p6, bB.x); ffma2(acc[6][3], p6, bB.y);
            ffma2(acc[7][0], p7, bA.x); ffma2(acc[7][1], p7, bA.y);
            ffma2(acc[7][2], p7, bB.x); ffma2(acc[7][3], p7, bB.y);
        }

        if (more) {
            const int nb = cb ^ 1;
            As[nb][lk+0][lr]=a0.x; As[nb][lk+1][lr]=a0.y; As[nb][lk+2][lr]=a0.z; As[nb][lk+3][lr]=a0.w;
            As[nb][lk+4][lr]=a1.x; As[nb][lk+5][lr]=a1.y; As[nb][lk+6][lr]=a1.z; As[nb][lk+7][lr]=a1.w;
            Bs[nb][lk+0][lr]=v0.x; Bs[nb][lk+1][lr]=v0.y; Bs[nb][lk+2][lr]=v0.z; Bs[nb][lk+3][lr]=v0.w;
            Bs[nb][lk+4][lr]=v1.x; Bs[nb][lk+5][lr]=v1.y; Bs[nb][lk+6][lr]=v1.z; Bs[nb][lk+7][lr]=v1.w;
        }
        __syncthreads();
    }

    float bias[8];
#pragma unroll
    for (int jj = 0; jj < 8; jj++) {
        int n = n0 + tx * 8 + jj;
        bias[jj] = (n < N) ? (b1[n] + (b2 ? b2[n] : 0.f)) : 0.f;
    }
    const int nbase = n0 + tx * 8;
    const bool full = (nbase + 8 <= N);
#pragma unroll
    for (int i = 0; i < 8; i++) {
        int m = m0 + ty * 8 + i;
        float *cp = C + (size_t)m * ldc;
        float v[8];
#pragma unroll
        for (int j = 0; j < 4; j++) {
            float lo, hi;
            unpack2(acc[i][j], lo, hi);
            v[2*j]   = lo + bias[2*j];
            v[2*j+1] = hi + bias[2*j+1];
        }
        if (full) {
            *reinterpret_cast<float4 *>(cp + nbase)     = make_float4(v[0], v[1], v[2], v[3]);
            *reinterpret_cast<float4 *>(cp + nbase + 4) = make_float4(v[4], v[5], v[6], v[7]);
        } else {
#pragma unroll
            for (int j = 0; j < 8; j++)
                if (nbase + j < N) cp[nbase + j] = v[j];
        }
    }
}

// ------------------------------------------------------------------
// GEMM small-N tile (R5-proven): BM=128, BN=64, BK=16, 256 thr, 4x8 tile.
// Used for projections (N=128 -> grid (2,128)=256 blocks, better occupancy).
// PERM: store row permutation m=(s*32+b) -> out row (b*512+s).
// ------------------------------------------------------------------
template <bool PERM>
__global__ __launch_bounds__(256)
void gemm_nt64(const float *__restrict__ A, const float *__restrict__ Bw,
               const float *__restrict__ b1,
               float *__restrict__ C, int M, int N, int K, int ldc) {
    __shared__ __align__(16) float As[16][132];
    __shared__ __align__(16) float Bs[16][68];

    const int tid = threadIdx.x;
    const int m0 = blockIdx.y * 128;
    const int n0 = blockIdx.x * 64;
    const int tx = tid & 7;
    const int ty = tid >> 3;
    const int a_r = tid >> 2;
    const int a_k = (tid & 3) * 4;

    unsigned long long acc[4][4];
#pragma unroll
    for (int i = 0; i < 4; i++)
#pragma unroll
        for (int j = 0; j < 4; j++) acc[i][j] = 0ULL;

    const int KT = (K + 15) >> 4;
    for (int kt = 0; kt < KT; kt++) {
        int k0 = kt * 16;
        float4 av0 = make_float4(0.f, 0.f, 0.f, 0.f);
        float4 av1 = av0, bv = av0;
        int kk = k0 + a_k;
        if (kk < K) {
            av0 = *reinterpret_cast<const float4 *>(A + (size_t)(m0 + a_r) * K + kk);
            av1 = *reinterpret_cast<const float4 *>(A + (size_t)(m0 + a_r + 64) * K + kk);
            if (n0 + a_r < N)
                bv = *reinterpret_cast<const float4 *>(Bw + (size_t)(n0 + a_r) * K + kk);
        }
        __syncthreads();
        As[a_k + 0][a_r] = av0.x; As[a_k + 1][a_r] = av0.y;
        As[a_k + 2][a_r] = av0.z; As[a_k + 3][a_r] = av0.w;
        As[a_k + 0][a_r + 64] = av1.x; As[a_k + 1][a_r + 64] = av1.y;
        As[a_k + 2][a_r + 64] = av1.z; As[a_k + 3][a_r + 64] = av1.w;
        Bs[a_k + 0][a_r] = bv.x; Bs[a_k + 1][a_r] = bv.y;
        Bs[a_k + 2][a_r] = bv.z; Bs[a_k + 3][a_r] = bv.w;
        __syncthreads();

#pragma unroll
        for (int k = 0; k < 16; k++) {
            float4 a4 = *reinterpret_cast<const float4 *>(&As[k][ty * 4]);
            const ulonglong2 *bp =
                reinterpret_cast<const ulonglong2 *>(&Bs[k][tx * 8]);
            ulonglong2 bA = bp[0], bB = bp[1];
            unsigned long long a0 = pack2(a4.x, a4.x);
            unsigned long long a1 = pack2(a4.y, a4.y);
            unsigned long long a2 = pack2(a4.z, a4.z);
            unsigned long long a3 = pack2(a4.w, a4.w);
            ffma2(acc[0][0], a0, bA.x); ffma2(acc[0][1], a0, bA.y);
            ffma2(acc[0][2], a0, bB.x); ffma2(acc[0][3], a0, bB.y);
            ffma2(acc[1][0], a1, bA.x); ffma2(acc[1][1], a1, bA.y);
            ffma2(acc[1][2], a1, bB.x); ffma2(acc[1][3], a1, bB.y);
            ffma2(acc[2][0], a2, bA.x); ffma2(acc[2][1], a2, bA.y);
            ffma2(acc[2][2], a2, bB.x); ffma2(acc[2][3], a2, bB.y);
            ffma2(acc[3][0], a3, bA.x); ffma2(acc[3][1], a3, bA.y);
            ffma2(acc[3][2], a3, bB.x); ffma2(acc[3][3], a3, bB.y);
        }
    }

    float bias[8];
#pragma unroll
    for (int jj = 0; jj < 8; jj++) {
        int n = n0 + tx * 8 + jj;
        bias[jj] = (n < N) ? b1[n] : 0.f;
    }
#pragma unroll
    for (int i = 0; i < 4; i++) {
        int m = m0 + ty * 4 + i;
        int row = PERM ? ((m & 31) * SS + (m >> 5)) : m;
        float *cp = C + (size_t)row * ldc;
#pragma unroll
        for (int j = 0; j < 4; j++) {
            int n = n0 + tx * 8 + 2 * j;
            float lo, hi;
            unpack2(acc[i][j], lo, hi);
            if (n < N)     cp[n]     = lo + bias[2 * j];
            if (n + 1 < N) cp[n + 1] = hi + bias[2 * j + 1];
        }
    }
}

// ------------------------------------------------------------------
// FUSED two-layer recurrence (R13 champion: interleaved dots, self-store
// fast path). CHANGE: AoS inbox layout [parity][slot][src] so a finalizer's
// 4 messages are one contiguous 32B group -> 2x vectorized volatile polls.
// Dynamic SMEM layout (bytes):
//   [0, 91200)        Whh2s[q][j] float4
//   [91200, 91840)    h1loc[2][80]
//   [91840, 92480)    h2loc[2][80]
//   [92480, 97344)    inbox1: [2][76][4] u64  (slot-major, src contiguous)
//   [97344, 102208)   inbox2: same
// ------------------------------------------------------------------
#define OFF_W    0
#define OFF_H1   91200
#define OFF_H2   91840
#define OFF_IB1  92480
#define OFF_IB2  97344
#define REC_SMEM 102208

__global__ void __cluster_dims__(4, 1, 1) __launch_bounds__(320, 1)
rec_fused(const float *__restrict__ Whh1, const float *__restrict__ Wih2,
          const float *__restrict__ Whh2, const float *__restrict__ bih2,
          const float *__restrict__ bhh2, const float *__restrict__ A,
          float *__restrict__ H1out, float *__restrict__ H2out) {
    extern __shared__ __align__(32) char smem[];
    float *h1loc = reinterpret_cast<float *>(smem + OFF_H1);           // [2][80]
    float *h2loc = reinterpret_cast<float *>(smem + OFF_H2);           // [2][80]
    unsigned long long *ib1 = reinterpret_cast<unsigned long long *>(smem + OFF_IB1);
    unsigned long long *ib2 = reinterpret_cast<unsigned long long *>(smem + OFF_IB2);

    const int tid  = threadIdx.x;
    const int rank = blockIdx.x & 3;
    const int b    = blockIdx.x >> 2;
    const bool active = tid < 300;
    const int dst  = active ? (tid / 75) : 0;
    const int slot = active ? (tid % 75) : 0;
    const bool self_dst = active && (dst == rank);

    // register-resident W slices: W_hh1[tid, 75r:+75], W_ih2[tid, 75r:+75]
    unsigned long long w1[38], wi[38];
    if (active) {
        const float *p1 = Whh1 + (size_t)tid * HH + rank * 75;
        const float *p2 = Wih2 + (size_t)tid * HH + rank * 75;
#pragma unroll
        for (int i = 0; i < 37; i++) {
            w1[i] = pack2(p1[2 * i], p1[2 * i + 1]);
            wi[i] = pack2(p2[2 * i], p2[2 * i + 1]);
        }
        w1[37] = pack2(p1[74], 0.f);
        wi[37] = pack2(p2[74], 0.f);
    }

    // fill Whh2s: entry e = q*300 + j  ->  float4 of W_hh2[j, 75r+4q .. +3]
    {
        float4 *Ws = reinterpret_cast<float4 *>(smem + OFF_W);
        for (int e = tid; e < 19 * 300; e += 320) {
            int q = e / 300, j = e - q * 300;
            const float *wp = Whh2 + (size_t)j * HH + rank * 75 + 4 * q;
            int c0 = 4 * q;
            float4 v;
            v.x = (c0 + 0 < 75) ? wp[0] : 0.f;
            v.y = (c0 + 1 < 75) ? wp[1] : 0.f;
            v.z = (c0 + 2 < 75) ? wp[2] : 0.f;
            v.w = (c0 + 3 < 75) ? wp[3] : 0.f;
            Ws[e] = v;
        }
    }
    for (int i = tid; i < 2 * 80; i += 320) { h1loc[i] = 0.f; h2loc[i] = 0.f; }
    for (int i = tid; i < 2 * 76 * 4; i += 320) {
        ib1[i] = 0xFFFFFFFF00000000ULL;
        ib2[i] = 0xFFFFFFFF00000000ULL;
    }
    __syncthreads();
    asm volatile("barrier.cluster.arrive.aligned;" ::: "memory");
    asm volatile("barrier.cluster.wait.aligned;" ::: "memory");

    // message addresses (AoS: index = (pb*76 + slot)*4 + src)
    unsigned in1_rem[2], in2_rem[2];
    volatile unsigned long long *in1_loc[2], *in2_loc[2];
    if (active) {
#pragma unroll
        for (int p = 0; p < 2; p++) {
            int idx = (p * 76 + slot) * 4 + rank;
            unsigned l1 = smem_u32(&ib1[idx]);
            unsigned l2 = smem_u32(&ib2[idx]);
            asm("mapa.shared::cluster.u32 %0, %1, %2;" : "=r"(in1_rem[p]) : "r"(l1), "r"(dst));
            asm("mapa.shared::cluster.u32 %0, %1, %2;" : "=r"(in2_rem[p]) : "r"(l2), "r"(dst));
            in1_loc[p] = &ib1[idx];
            in2_loc[p] = &ib2[idx];
        }
    }
    // finalizer poll base addresses (32B group per slot)
    const bool fin1 = (tid < 75);
    const bool fin2 = (tid >= 96 && tid < 171);
    const int  sl2  = tid - 96;
    unsigned poll1[2], poll2[2];
    if (fin1) {
#pragma unroll
        for (int p = 0; p < 2; p++)
            poll1[p] = smem_u32(&ib1[(p * 76 + tid) * 4]);
    }
    float bias2 = 0.f;
    if (fin2) {
#pragma unroll
        for (int p = 0; p < 2; p++)
            poll2[p] = smem_u32(&ib2[(p * 76 + sl2) * 4]);
        int row = 75 * rank + sl2;
        bias2 = bih2[row] + bhh2[row];
    }

    const float *arow = A + (size_t)b * HH + rank * 75;
    float *h1row = H1out + (size_t)b * HH + rank * 75;
    float *h2row = H2out + (size_t)b * HH + rank * 75;
    const ulonglong2 *Ws2 = reinterpret_cast<const ulonglong2 *>(smem + OFF_W);

    float a_cur = fin1 ? arow[tid] : 0.f;

    for (int t = 0; t <= SS; t++) {
        const int pb = t & 1;
        float a_nxt = 0.f;
        if (fin1 && t + 1 < SS)
            a_nxt = arow[(size_t)(t + 1) * BB * HH + tid];

        if (active) {
            // interleaved dots (champion): L1, W_ih2, W_hh2 in one loop
            const ulonglong2 *hp1 =
                reinterpret_cast<const ulonglong2 *>(&h1loc[(pb ^ 1) * 80]);
            const ulonglong2 *hp2 =
                reinterpret_cast<const ulonglong2 *>(&h2loc[pb * 80]);   // h2_{t-2}
            unsigned long long c0 = 0, c1 = 0, d0 = 0, d1 = 0, e0 = 0, e1 = 0;
#pragma unroll
            for (int k = 0; k < 19; k++) {
                ulonglong2 hv = hp1[k];
                ffma2(c0, w1[2 * k], hv.x); ffma2(c1, w1[2 * k + 1], hv.y);
                ffma2(d0, wi[2 * k], hv.x); ffma2(d1, wi[2 * k + 1], hv.y);
                ulonglong2 wv = Ws2[k * 300 + tid];
                ulonglong2 h2v = hp2[k];
                ffma2(e0, wv.x, h2v.x); ffma2(e1, wv.y, h2v.y);
            }
            float x0, x1, y0, y1;
            unpack2(c0, x0, x1); unpack2(c1, y0, y1);
            float p1v = (x0 + x1) + (y0 + y1);
            unpack2(d0, x0, x1); unpack2(d1, y0, y1);
            float piv = (x0 + x1) + (y0 + y1);
            unpack2(e0, x0, x1); unpack2(e1, y0, y1);
            float p2v = piv + (x0 + x1) + (y0 + y1);

            if (t < SS) {
                unsigned long long msg;
                asm("mov.b64 %0, {%1, %2};"
                    : "=l"(msg) : "r"(__float_as_uint(p1v)), "r"((unsigned)t));
                if (self_dst) {
                    *in1_loc[pb] = msg;                        // local fast path
                } else {
                    asm volatile("st.relaxed.cluster.shared::cluster.b64 [%0], %1;"
                                 :: "r"(in1_rem[pb]), "l"(msg) : "memory");
                }
            }
            if (t >= 1) {
                unsigned long long msg;
                asm("mov.b64 %0, {%1, %2};"
                    : "=l"(msg) : "r"(__float_as_uint(p2v)), "r"((unsigned)t));
                if (self_dst) {
                    *in2_loc[pb] = msg;                        // local fast path
                } else {
                    asm volatile("st.relaxed.cluster.shared::cluster.b64 [%0], %1;"
                                 :: "r"(in2_rem[pb]), "l"(msg) : "memory");
                }
            }
        }

        if (fin1 && t < SS) {
            const unsigned want = (unsigned)t;
            unsigned long long v0, v1, v2, v3;
            do {
                asm volatile("ld.volatile.shared.v2.u64 {%0,%1}, [%2];"
                             : "=l"(v0), "=l"(v1) : "r"(poll1[pb]) : "memory");
                asm volatile("ld.volatile.shared.v2.u64 {%0,%1}, [%2];"
                             : "=l"(v2), "=l"(v3) : "r"(poll1[pb] + 16) : "memory");
            } while (((unsigned)(v0 >> 32) != want) | ((unsigned)(v1 >> 32) != want) |
                     ((unsigned)(v2 >> 32) != want) | ((unsigned)(v3 >> 32) != want));
            float s = a_cur + __uint_as_float((unsigned)v0)
                            + __uint_as_float((unsigned)v1)
                            + __uint_as_float((unsigned)v2)
                            + __uint_as_float((unsigned)v3);
            float hv = tanh_fast(s);
            h1row[(size_t)t * BB * HH + tid] = hv;
            h1loc[pb * 80 + tid] = hv;
        }
        if (fin2 && t >= 1) {
            const unsigned want = (unsigned)t;
            unsigned long long v0, v1, v2, v3;
            do {
                asm volatile("ld.volatile.shared.v2.u64 {%0,%1}, [%2];"
                             : "=l"(v0), "=l"(v1) : "r"(poll2[pb]) : "memory");
                asm volatile("ld.volatile.shared.v2.u64 {%0,%1}, [%2];"
                             : "=l"(v2), "=l"(v3) : "r"(poll2[pb] + 16) : "memory");
            } while (((unsigned)(v0 >> 32) != want) | ((unsigned)(v1 >> 32) != want) |
                     ((unsigned)(v2 >> 32) != want) | ((unsigned)(v3 >> 32) != want));
            float s = bias2 + __uint_as_float((unsigned)v0)
                            + __uint_as_float((unsigned)v1)
                            + __uint_as_float((unsigned)v2)
                            + __uint_as_float((unsigned)v3);
            float hv = tanh_fast(s);
            h2row[(size_t)(t - 1) * BB * HH + sl2] = hv;
            h2loc[(pb ^ 1) * 80 + sl2] = hv;   // read as h2_{(t+1)-2} next step
        }
        a_cur = a_nxt;
        __syncthreads();
    }

    asm volatile("barrier.cluster.arrive.aligned;" ::: "memory");
    asm volatile("barrier.cluster.wait.aligned;" ::: "memory");
}

// ------------------------------------------------------------------
// Launch sequence
// ------------------------------------------------------------------
extern "C" void kernel_launch(void *const *d_in, const int *in_sizes, int n_in,
                              void *d_out, int out_size) {
    const int   *x     = (const int *)d_in[0];
    const float *emb   = (const float *)d_in[1];
    const float *W_ih1 = (const float *)d_in[2];
    const float *W_hh1 = (const float *)d_in[3];
    const float *b_ih1 = (const float *)d_in[4];
    const float *b_hh1 = (const float *)d_in[5];
    const float *W_ih2 = (const float *)d_in[6];
    const float *W_hh2 = (const float *)d_in[7];
    const float *b_ih2 = (const float *)d_in[8];
    const float *b_hh2 = (const float *)d_in[9];
    const float *fc1_w = (const float *)d_in[10];
    const float *fc1_b = (const float *)d_in[11];
    const float *fc2_w = (const float *)d_in[12];
    const float *fc2_b = (const float *)d_in[13];
    float *out = (float *)d_out;

    float *xe, *a, *h1, *h2;
    cudaGetSymbolAddress((void **)&xe, g_XE);
    cudaGetSymbolAddress((void **)&a,  g_A);
    cudaGetSymbolAddress((void **)&h1, g_H1);
    cudaGetSymbolAddress((void **)&h2, g_H2);

    static int smem_set = 0;
    if (!smem_set) {
        cudaFuncSetAttribute(rec_fused,
                             cudaFuncAttributeMaxDynamicSharedMemorySize,
                             REC_SMEM);
        smem_set = 1;
    }

    // 1) embed + relu
    embed_kernel<<<MROWS, 128>>>(x, emb);

    // 2) A1 = XE @ W_ih1^T + (b_ih1 + b_hh1)
    {
        dim3 grid((HH + 127) / 128, MROWS / 128);
        gemm_nt<<<grid, 256>>>(xe, W_ih1, b_ih1, b_hh1, a,
                               MROWS, HH, K1, HH);
    }

    // 3) fused two-layer recurrence -> H1, H2
    rec_fused<<<128, 320, REC_SMEM>>>(W_hh1, W_ih2, W_hh2, b_ih2, b_hh2,
                                      a, h1, h2);

    // 4) projections with BN=64 tile (grid 256 blocks -> better occupancy)
    {
        dim3 grid((NOUT + 63) / 64, MROWS / 128);
        gemm_nt64<true><<<grid, 256>>>(h1, fc1_w, fc1_b, out,
                                       MROWS, NOUT, HH, NOUT);
        gemm_nt64<true><<<grid, 256>>>(h2, fc2_w, fc2_b,
                                       out + (size_t)MROWS * NOUT,
                                       MROWS, NOUT, HH, NOUT);
    }
}

// round 16
// speedup vs baseline: 1.1642x; 1.0211x over previous
#include <cuda_runtime.h>
#include <cuda_bf16.h>

// Problem dims
#define BB    32
#define SS    512
#define WIN   5
#define EMB   300
#define HH    300
#define K1    1500        // EMB*WIN
#define NOUT  128
#define MROWS (BB*SS)     // 16384

// ------------------------------------------------------------------
// Scratch (static device globals)
// ------------------------------------------------------------------
__device__ float g_XE[(size_t)MROWS * K1];   // relu(embedded)
__device__ float g_A [(size_t)MROWS * HH];   // A1 pre-activation
__device__ float g_H1[(size_t)MROWS * HH];   // layer1 hidden states [s*32+b][300]
__device__ float g_H2[(size_t)MROWS * HH];   // layer2 hidden states

// ------------------------------------------------------------------
// helpers
// ------------------------------------------------------------------
__device__ __forceinline__ void ffma2(unsigned long long &d,
                                      unsigned long long a,
                                      unsigned long long b) {
    asm("fma.rn.f32x2 %0, %1, %2, %0;" : "+l"(d) : "l"(a), "l"(b));
}
__device__ __forceinline__ unsigned long long pack2(float lo, float hi) {
    unsigned long long r;
    asm("mov.b64 %0, {%1, %2};" : "=l"(r) : "f"(lo), "f"(hi));
    return r;
}
__device__ __forceinline__ void unpack2(unsigned long long v, float &lo, float &hi) {
    asm("mov.b64 {%0, %1}, %2;" : "=f"(lo), "=f"(hi) : "l"(v));
}
__device__ __forceinline__ unsigned smem_u32(const void *p) {
    unsigned a;
    asm("{ .reg .u64 t; cvta.to.shared.u64 t, %1; cvt.u32.u64 %0, t; }"
        : "=r"(a) : "l"(p));
    return a;
}
// tanh via MUFU: 1 - 2/(exp2(2x*log2e)+1). abs err ~1e-7, no division.
__device__ __forceinline__ float tanh_fast(float x) {
    float e;
    asm("ex2.approx.f32 %0, %1;" : "=f"(e) : "f"(x * 2.88539008177792681f));
    float r;
    asm("rcp.approx.f32 %0, %1;" : "=f"(r) : "f"(e + 1.0f));
    return fmaf(-2.0f, r, 1.0f);
}

// ------------------------------------------------------------------
// Kernel 1: embedding gather + relu
// ------------------------------------------------------------------
__global__ void embed_kernel(const int *__restrict__ x,
                             const float *__restrict__ emb) {
    int m = blockIdx.x;            // m = s*32 + b
    int s = m >> 5, b = m & 31;
    __shared__ int idx[WIN];
    if (threadIdx.x < WIN) idx[threadIdx.x] = x[(b * SS + s) * WIN + threadIdx.x];
    __syncthreads();
    float4 *out4 = reinterpret_cast<float4 *>(g_XE + (size_t)m * K1);
    for (int i = threadIdx.x; i < K1 / 4; i += blockDim.x) {
        int e4 = i * 4;
        int w = e4 / EMB;
        int e = e4 - w * EMB;
        float4 v = *reinterpret_cast<const float4 *>(emb + (size_t)idx[w] * EMB + e);
        v.x = fmaxf(v.x, 0.f); v.y = fmaxf(v.y, 0.f);
        v.z = fmaxf(v.z, 0.f); v.w = fmaxf(v.w, 0.f);
        out4[i] = v;
    }
}

// ------------------------------------------------------------------
// GEMM (proven R8): BM=128, BN=128, BK=16, 256 thr, 8x8 tile, dbl-buffered.
// PERM: store row permutation m=(s*32+b) -> out row (b*512+s).
// ------------------------------------------------------------------
template <bool PERM>
__global__ __launch_bounds__(256)
void gemm_nt(const float *__restrict__ A, const float *__restrict__ Bw,
             const float *__restrict__ b1, const float *__restrict__ b2,
             float *__restrict__ C, int M, int N, int K, int ldc) {
    __shared__ __align__(16) float As[2][16][132];
    __shared__ __align__(16) float Bs[2][16][132];

    const int tid = threadIdx.x;
    const int m0 = blockIdx.y * 128;
    const int n0 = blockIdx.x * 128;
    const int tx = tid & 15;
    const int ty = tid >> 4;
    const int lr = tid >> 1;
    const int lk = (tid & 1) * 8;

    unsigned long long acc[8][4];
#pragma unroll
    for (int i = 0; i < 8; i++)
#pragma unroll
        for (int j = 0; j < 4; j++) acc[i][j] = 0ULL;

    const int KT = (K + 15) >> 4;

    {
        float4 a0 = make_float4(0.f,0.f,0.f,0.f), a1 = a0, v0 = a0, v1 = a0;
        int kk = lk;
        const float *ap = A + (size_t)(m0 + lr) * K;
        if (kk     < K) a0 = *reinterpret_cast<const float4 *>(ap + kk);
        if (kk + 4 < K) a1 = *reinterpret_cast<const float4 *>(ap + kk + 4);
        if (n0 + lr < N) {
            const float *bp = Bw + (size_t)(n0 + lr) * K;
            if (kk     < K) v0 = *reinterpret_cast<const float4 *>(bp + kk);
            if (kk + 4 < K) v1 = *reinterpret_cast<const float4 *>(bp + kk + 4);
        }
        As[0][lk+0][lr]=a0.x; As[0][lk+1][lr]=a0.y; As[0][lk+2][lr]=a0.z; As[0][lk+3][lr]=a0.w;
        As[0][lk+4][lr]=a1.x; As[0][lk+5][lr]=a1.y; As[0][lk+6][lr]=a1.z; As[0][lk+7][lr]=a1.w;
        Bs[0][lk+0][lr]=v0.x; Bs[0][lk+1][lr]=v0.y; Bs[0][lk+2][lr]=v0.z; Bs[0][lk+3][lr]=v0.w;
        Bs[0][lk+4][lr]=v1.x; Bs[0][lk+5][lr]=v1.y; Bs[0][lk+6][lr]=v1.z; Bs[0][lk+7][lr]=v1.w;
    }
    __syncthreads();

    for (int kt = 0; kt < KT; kt++) {
        const int cb = kt & 1;
        float4 a0 = make_float4(0.f,0.f,0.f,0.f), a1 = a0, v0 = a0, v1 = a0;
        const bool more = (kt + 1 < KT);
        if (more) {
            int kk = (kt + 1) * 16 + lk;
            const float *ap = A + (size_t)(m0 + lr) * K;
            if (kk     < K) a0 = *reinterpret_cast<const float4 *>(ap + kk);
            if (kk + 4 < K) a1 = *reinterpret_cast<const float4 *>(ap + kk + 4);
            if (n0 + lr < N) {
                const float *bp = Bw + (size_t)(n0 + lr) * K;
                if (kk     < K) v0 = *reinterpret_cast<const float4 *>(bp + kk);
                if (kk + 4 < K) v1 = *reinterpret_cast<const float4 *>(bp + kk + 4);
            }
        }

#pragma unroll
        for (int k = 0; k < 16; k++) {
            float4 aA = *reinterpret_cast<const float4 *>(&As[cb][k][ty * 8]);
            float4 aB = *reinterpret_cast<const float4 *>(&As[cb][k][ty * 8 + 4]);
            ulonglong2 bA = *reinterpret_cast<const ulonglong2 *>(&Bs[cb][k][tx * 8]);
            ulonglong2 bB = *reinterpret_cast<const ulonglong2 *>(&Bs[cb][k][tx * 8 + 4]);
            unsigned long long p0 = pack2(aA.x, aA.x), p1 = pack2(aA.y, aA.y);
            unsigned long long p2 = pack2(aA.z, aA.z), p3 = pack2(aA.w, aA.w);
            unsigned long long p4 = pack2(aB.x, aB.x), p5 = pack2(aB.y, aB.y);
            unsigned long long p6 = pack2(aB.z, aB.z), p7 = pack2(aB.w, aB.w);
            ffma2(acc[0][0], p0, bA.x); ffma2(acc[0][1], p0, bA.y);
            ffma2(acc[0][2], p0, bB.x); ffma2(acc[0][3], p0, bB.y);
            ffma2(acc[1][0], p1, bA.x); ffma2(acc[1][1], p1, bA.y);
            ffma2(acc[1][2], p1, bB.x); ffma2(acc[1][3], p1, bB.y);
            ffma2(acc[2][0], p2, bA.x); ffma2(acc[2][1], p2, bA.y);
            ffma2(acc[2][2], p2, bB.x); ffma2(acc[2][3], p2, bB.y);
            ffma2(acc[3][0], p3, bA.x); ffma2(acc[3][1], p3, bA.y);
            ffma2(acc[3][2], p3, bB.x); ffma2(acc[3][3], p3, bB.y);
            ffma2(acc[4][0], p4, bA.x); ffma2(acc[4][1], p4, bA.y);
            ffma2(acc[4][2], p4, bB.x); ffma2(acc[4][3], p4, bB.y);
            ffma2(acc[5][0], p5, bA.x); ffma2(acc[5][1], p5, bA.y);
            ffma2(acc[5][2], p5, bB.x); ffma2(acc[5][3], p5, bB.y);
            ffma2(acc[6][0], p6, bA.x); ffma2(acc[6][1], p6, bA.y);
            ffma2(acc[6][2], p6, bB.x); ffma2(acc[6][3], p6, bB.y);
            ffma2(acc[7][0], p7, bA.x); ffma2(acc[7][1], p7, bA.y);
            ffma2(acc[7][2], p7, bB.x); ffma2(acc[7][3], p7, bB.y);
        }

        if (more) {
            const int nb = cb ^ 1;
            As[nb][lk+0][lr]=a0.x; As[nb][lk+1][lr]=a0.y; As[nb][lk+2][lr]=a0.z; As[nb][lk+3][lr]=a0.w;
            As[nb][lk+4][lr]=a1.x; As[nb][lk+5][lr]=a1.y; As[nb][lk+6][lr]=a1.z; As[nb][lk+7][lr]=a1.w;
            Bs[nb][lk+0][lr]=v0.x; Bs[nb][lk+1][lr]=v0.y; Bs[nb][lk+2][lr]=v0.z; Bs[nb][lk+3][lr]=v0.w;
            Bs[nb][lk+4][lr]=v1.x; Bs[nb][lk+5][lr]=v1.y; Bs[nb][lk+6][lr]=v1.z; Bs[nb][lk+7][lr]=v1.w;
        }
        __syncthreads();
    }

    float bias[8];
#pragma unroll
    for (int jj = 0; jj < 8; jj++) {
        int n = n0 + tx * 8 + jj;
        bias[jj] = (n < N) ? (b1[n] + (b2 ? b2[n] : 0.f)) : 0.f;
    }
    const int nbase = n0 + tx * 8;
    const bool full = (nbase + 8 <= N);
#pragma unroll
    for (int i = 0; i < 8; i++) {
        int m = m0 + ty * 8 + i;
        int row = PERM ? ((m & 31) * SS + (m >> 5)) : m;
        float *cp = C + (size_t)row * ldc;
        float v[8];
#pragma unroll
        for (int j = 0; j < 4; j++) {
            float lo, hi;
            unpack2(acc[i][j], lo, hi);
            v[2*j]   = lo + bias[2*j];
            v[2*j+1] = hi + bias[2*j+1];
        }
        if (full) {
            *reinterpret_cast<float4 *>(cp + nbase)     = make_float4(v[0], v[1], v[2], v[3]);
            *reinterpret_cast<float4 *>(cp + nbase + 4) = make_float4(v[4], v[5], v[6], v[7]);
        } else {
#pragma unroll
            for (int j = 0; j < 8; j++)
                if (nbase + j < N) cp[nbase + j] = v[j];
        }
    }
}

// ------------------------------------------------------------------
// FUSED two-layer recurrence. R15 champion (interleaved dots, self-store
// fast path, AoS vectorized polls) + one change:
//   fin1 = SELF-PRODUCER threads [75*rank, 75*rank+75): the h1 finalizer
//   reads its OWN store of the self partial (same-thread program order =>
//   immediately visible with fresh tag) -> removes one cross-thread
//   visibility wait from the h1 serial chain.
//   fin2 = threads [75*((rank+2)&3), +75) (always disjoint from fin1).
// SMEM layout unchanged: inbox AoS [parity][slot][src].
// ------------------------------------------------------------------
#define OFF_W    0
#define OFF_H1   91200
#define OFF_H2   91840
#define OFF_IB1  92480
#define OFF_IB2  97344
#define REC_SMEM 102208

__global__ void __cluster_dims__(4, 1, 1) __launch_bounds__(320, 1)
rec_fused(const float *__restrict__ Whh1, const float *__restrict__ Wih2,
          const float *__restrict__ Whh2, const float *__restrict__ bih2,
          const float *__restrict__ bhh2, const float *__restrict__ A,
          float *__restrict__ H1out, float *__restrict__ H2out) {
    extern __shared__ __align__(32) char smem[];
    float *h1loc = reinterpret_cast<float *>(smem + OFF_H1);           // [2][80]
    float *h2loc = reinterpret_cast<float *>(smem + OFF_H2);           // [2][80]
    unsigned long long *ib1 = reinterpret_cast<unsigned long long *>(smem + OFF_IB1);
    unsigned long long *ib2 = reinterpret_cast<unsigned long long *>(smem + OFF_IB2);

    const int tid  = threadIdx.x;
    const int rank = blockIdx.x & 3;
    const int b    = blockIdx.x >> 2;
    const bool active = tid < 300;
    const int dst  = active ? (tid / 75) : 0;
    const int slot = active ? (tid % 75) : 0;
    const bool self_dst = active && (dst == rank);

    // register-resident W slices: W_hh1[tid, 75r:+75], W_ih2[tid, 75r:+75]
    unsigned long long w1[38], wi[38];
    if (active) {
        const float *p1 = Whh1 + (size_t)tid * HH + rank * 75;
        const float *p2 = Wih2 + (size_t)tid * HH + rank * 75;
#pragma unroll
        for (int i = 0; i < 37; i++) {
            w1[i] = pack2(p1[2 * i], p1[2 * i + 1]);
            wi[i] = pack2(p2[2 * i], p2[2 * i + 1]);
        }
        w1[37] = pack2(p1[74], 0.f);
        wi[37] = pack2(p2[74], 0.f);
    }

    // fill Whh2s: entry e = q*300 + j  ->  float4 of W_hh2[j, 75r+4q .. +3]
    {
        float4 *Ws = reinterpret_cast<float4 *>(smem + OFF_W);
        for (int e = tid; e < 19 * 300; e += 320) {
            int q = e / 300, j = e - q * 300;
            const float *wp = Whh2 + (size_t)j * HH + rank * 75 + 4 * q;
            int c0 = 4 * q;
            float4 v;
            v.x = (c0 + 0 < 75) ? wp[0] : 0.f;
            v.y = (c0 + 1 < 75) ? wp[1] : 0.f;
            v.z = (c0 + 2 < 75) ? wp[2] : 0.f;
            v.w = (c0 + 3 < 75) ? wp[3] : 0.f;
            Ws[e] = v;
        }
    }
    for (int i = tid; i < 2 * 80; i += 320) { h1loc[i] = 0.f; h2loc[i] = 0.f; }
    for (int i = tid; i < 2 * 76 * 4; i += 320) {
        ib1[i] = 0xFFFFFFFF00000000ULL;
        ib2[i] = 0xFFFFFFFF00000000ULL;
    }
    __syncthreads();
    asm volatile("barrier.cluster.arrive.aligned;" ::: "memory");
    asm volatile("barrier.cluster.wait.aligned;" ::: "memory");

    // message addresses (AoS: index = (pb*76 + slot)*4 + src)
    unsigned in1_rem[2], in2_rem[2];
    volatile unsigned long long *in1_loc[2], *in2_loc[2];
    if (active) {
#pragma unroll
        for (int p = 0; p < 2; p++) {
            int idx = (p * 76 + slot) * 4 + rank;
            unsigned l1 = smem_u32(&ib1[idx]);
            unsigned l2 = smem_u32(&ib2[idx]);
            asm("mapa.shared::cluster.u32 %0, %1, %2;" : "=r"(in1_rem[p]) : "r"(l1), "r"(dst));
            asm("mapa.shared::cluster.u32 %0, %1, %2;" : "=r"(in2_rem[p]) : "r"(l2), "r"(dst));
            in1_loc[p] = &ib1[idx];
            in2_loc[p] = &ib2[idx];
        }
    }
    // finalizer assignment:
    //   fin1 = self-producer range [75*rank, +75)   (sl1 = slot)
    //   fin2 = range of ((rank+2)&3)                (sl2 = slot there)
    const bool fin1 = active && (dst == rank);
    const int  sl1  = slot;
    const int  r2   = (rank + 2) & 3;
    const bool fin2 = active && (dst == r2);
    const int  sl2  = slot;
    unsigned poll1[2], poll2[2];
    if (fin1) {
#pragma unroll
        for (int p = 0; p < 2; p++)
            poll1[p] = smem_u32(&ib1[(p * 76 + sl1) * 4]);
    }
    float bias2 = 0.f;
    if (fin2) {
#pragma unroll
        for (int p = 0; p < 2; p++)
            poll2[p] = smem_u32(&ib2[(p * 76 + sl2) * 4]);
        int row = 75 * rank + sl2;
        bias2 = bih2[row] + bhh2[row];
    }

    const float *arow = A + (size_t)b * HH + rank * 75;
    float *h1row = H1out + (size_t)b * HH + rank * 75;
    float *h2row = H2out + (size_t)b * HH + rank * 75;
    const ulonglong2 *Ws2 = reinterpret_cast<const ulonglong2 *>(smem + OFF_W);

    float a_cur = fin1 ? arow[sl1] : 0.f;

    for (int t = 0; t <= SS; t++) {
        const int pb = t & 1;
        float a_nxt = 0.f;
        if (fin1 && t + 1 < SS)
            a_nxt = arow[(size_t)(t + 1) * BB * HH + sl1];

        if (active) {
            // interleaved dots (champion): L1, W_ih2, W_hh2 in one loop
            const ulonglong2 *hp1 =
                reinterpret_cast<const ulonglong2 *>(&h1loc[(pb ^ 1) * 80]);
            const ulonglong2 *hp2 =
                reinterpret_cast<const ulonglong2 *>(&h2loc[pb * 80]);   // h2_{t-2}
            unsigned long long c0 = 0, c1 = 0, d0 = 0, d1 = 0, e0 = 0, e1 = 0;
#pragma unroll
            for (int k = 0; k < 19; k++) {
                ulonglong2 hv = hp1[k];
                ffma2(c0, w1[2 * k], hv.x); ffma2(c1, w1[2 * k + 1], hv.y);
                ffma2(d0, wi[2 * k], hv.x); ffma2(d1, wi[2 * k + 1], hv.y);
                ulonglong2 wv = Ws2[k * 300 + tid];
                ulonglong2 h2v = hp2[k];
                ffma2(e0, wv.x, h2v.x); ffma2(e1, wv.y, h2v.y);
            }
            float x0, x1, y0, y1;
            unpack2(c0, x0, x1); unpack2(c1, y0, y1);
            float p1v = (x0 + x1) + (y0 + y1);
            unpack2(d0, x0, x1); unpack2(d1, y0, y1);
            float piv = (x0 + x1) + (y0 + y1);
            unpack2(e0, x0, x1); unpack2(e1, y0, y1);
            float p2v = piv + (x0 + x1) + (y0 + y1);

            if (t < SS) {
                unsigned long long msg;
                asm("mov.b64 %0, {%1, %2};"
                    : "=l"(msg) : "r"(__float_as_uint(p1v)), "r"((unsigned)t));
                if (self_dst) {
                    *in1_loc[pb] = msg;                        // own-slot store
                } else {
                    asm volatile("st.relaxed.cluster.shared::cluster.b64 [%0], %1;"
                                 :: "r"(in1_rem[pb]), "l"(msg) : "memory");
                }
            }
            if (t >= 1) {
                unsigned long long msg;
                asm("mov.b64 %0, {%1, %2};"
                    : "=l"(msg) : "r"(__float_as_uint(p2v)), "r"((unsigned)t));
                if (self_dst) {
                    *in2_loc[pb] = msg;
                } else {
                    asm volatile("st.relaxed.cluster.shared::cluster.b64 [%0], %1;"
                                 :: "r"(in2_rem[pb]), "l"(msg) : "memory");
                }
            }
        }

        if (fin1 && t < SS) {
            const unsigned want = (unsigned)t;
            unsigned long long v0, v1, v2, v3;
            do {
                asm volatile("ld.volatile.shared.v2.u64 {%0,%1}, [%2];"
                             : "=l"(v0), "=l"(v1) : "r"(poll1[pb]) : "memory");
                asm volatile("ld.volatile.shared.v2.u64 {%0,%1}, [%2];"
                             : "=l"(v2), "=l"(v3) : "r"(poll1[pb] + 16) : "memory");
            } while (((unsigned)(v0 >> 32) != want) | ((unsigned)(v1 >> 32) != want) |
                     ((unsigned)(v2 >> 32) != want) | ((unsigned)(v3 >> 32) != want));
            float s = a_cur + __uint_as_float((unsigned)v0)
                            + __uint_as_float((unsigned)v1)
                            + __uint_as_float((unsigned)v2)
                            + __uint_as_float((unsigned)v3);
            float hv = tanh_fast(s);
            h1row[(size_t)t * BB * HH + sl1] = hv;
            h1loc[pb * 80 + sl1] = hv;
        }
        if (fin2 && t >= 1) {
            const unsigned want = (unsigned)t;
            unsigned long long v0, v1, v2, v3;
            do {
                asm volatile("ld.volatile.shared.v2.u64 {%0,%1}, [%2];"
                             : "=l"(v0), "=l"(v1) : "r"(poll2[pb]) : "memory");
                asm volatile("ld.volatile.shared.v2.u64 {%0,%1}, [%2];"
                             : "=l"(v2), "=l"(v3) : "r"(poll2[pb] + 16) : "memory");
            } while (((unsigned)(v0 >> 32) != want) | ((unsigned)(v1 >> 32) != want) |
                     ((unsigned)(v2 >> 32) != want) | ((unsigned)(v3 >> 32) != want));
            float s = bias2 + __uint_as_float((unsigned)v0)
                            + __uint_as_float((unsigned)v1)
                            + __uint_as_float((unsigned)v2)
                            + __uint_as_float((unsigned)v3);
            float hv = tanh_fast(s);
            h2row[(size_t)(t - 1) * BB * HH + sl2] = hv;
            h2loc[(pb ^ 1) * 80 + sl2] = hv;   // read as h2_{(t+1)-2} next step
        }
        a_cur = a_nxt;
        __syncthreads();
    }

    asm volatile("barrier.cluster.arrive.aligned;" ::: "memory");
    asm volatile("barrier.cluster.wait.aligned;" ::: "memory");
}

// ------------------------------------------------------------------
// Launch sequence
// ------------------------------------------------------------------
extern "C" void kernel_launch(void *const *d_in, const int *in_sizes, int n_in,
                              void *d_out, int out_size) {
    const int   *x     = (const int *)d_in[0];
    const float *emb   = (const float *)d_in[1];
    const float *W_ih1 = (const float *)d_in[2];
    const float *W_hh1 = (const float *)d_in[3];
    const float *b_ih1 = (const float *)d_in[4];
    const float *b_hh1 = (const float *)d_in[5];
    const float *W_ih2 = (const float *)d_in[6];
    const float *W_hh2 = (const float *)d_in[7];
    const float *b_ih2 = (const float *)d_in[8];
    const float *b_hh2 = (const float *)d_in[9];
    const float *fc1_w = (const float *)d_in[10];
    const float *fc1_b = (const float *)d_in[11];
    const float *fc2_w = (const float *)d_in[12];
    const float *fc2_b = (const float *)d_in[13];
    float *out = (float *)d_out;

    float *xe, *a, *h1, *h2;
    cudaGetSymbolAddress((void **)&xe, g_XE);
    cudaGetSymbolAddress((void **)&a,  g_A);
    cudaGetSymbolAddress((void **)&h1, g_H1);
    cudaGetSymbolAddress((void **)&h2, g_H2);

    static int smem_set = 0;
    if (!smem_set) {
        cudaFuncSetAttribute(rec_fused,
                             cudaFuncAttributeMaxDynamicSharedMemorySize,
                             REC_SMEM);
        smem_set = 1;
    }

    // 1) embed + relu
    embed_kernel<<<MROWS, 128>>>(x, emb);

    // 2) A1 = XE @ W_ih1^T + (b_ih1 + b_hh1)
    {
        dim3 grid((HH + 127) / 128, MROWS / 128);
        gemm_nt<false><<<grid, 256>>>(xe, W_ih1, b_ih1, b_hh1, a,
                                      MROWS, HH, K1, HH);
    }

    // 3) fused two-layer recurrence -> H1, H2
    rec_fused<<<128, 320, REC_SMEM>>>(W_hh1, W_ih2, W_hh2, b_ih2, b_hh2,
                                      a, h1, h2);

    // 4) projections with proven BM128/BN128 tile (50us each)
    {
        dim3 grid((NOUT + 127) / 128, MROWS / 128);
        gemm_nt<true><<<grid, 256>>>(h1, fc1_w, fc1_b, nullptr, out,
                                     MROWS, NOUT, HH, NOUT);
        gemm_nt<true><<<grid, 256>>>(h2, fc2_w, fc2_b, nullptr,
                                     out + (size_t)MROWS * NOUT,
                                     MROWS, NOUT, HH, NOUT);
    }
}